// round 2
// baseline (speedup 1.0000x reference)
#include <cuda_runtime.h>
#include <cstdint>

// Problem constants (fixed by the reference setup)
#define NV 150000          // total active voxels
#define SZc 41
#define SYc 1600
#define SXc 1408
#define HBITS 19
#define HSIZE (1 << HBITS) // 524288 hash slots (load factor ~0.29)
#define HMASK (HSIZE - 1)
#define BSHIFT 13
#define NBK 45100          // number of rank buckets = MAXLIN >> 13
#define NRED 128           // BN reduction blocks

// ---------------- static device scratch (no runtime allocation) ----------------
__device__ int   g_hkey[HSIZE];
__device__ int   g_hval[HSIZE];
__device__ int   g_lin[NV];
__device__ int   g_cnt[NV];
__device__ int   g_nbr[NV * 27];     // packed (k<<18)|row
__device__ int   g_hist[NBK];
__device__ int   g_scan[NBK + 1];
__device__ int   g_bfill[NBK];
__device__ int   g_blin[NV];
__device__ float g_y0[NV * 16];
__device__ float g_x[NV * 16];
__device__ float g_xa[NV * 16];
__device__ float g_part[NRED * 32];
__device__ float g_ss[4][16];        // [0]=scale0 [1]=shift0 [2]=scale1 [3]=shift1

// ---------------- init: clear hash keys + histograms ----------------
__global__ void k_init() {
    int i = blockIdx.x * blockDim.x + threadIdx.x;
    if (i < HSIZE) g_hkey[i] = -1;
    if (i < NBK) { g_hist[i] = 0; g_bfill[i] = 0; }
}

__device__ __forceinline__ unsigned hash_of(int key) {
    return ((unsigned)key * 2654435761u) >> (32 - HBITS);
}

// ---------------- build: linearize, hash-insert, bucket histogram ----------------
__global__ void k_build(const int* __restrict__ inds) {
    int j = blockIdx.x * blockDim.x + threadIdx.x;
    if (j >= NV) return;
    int4 id = reinterpret_cast<const int4*>(inds)[j];
    int l = ((id.x * SZc + id.y) * SYc + id.z) * SXc + id.w;
    g_lin[j] = l;
    unsigned slot = hash_of(l);
    while (true) {
        int old = atomicCAS(&g_hkey[slot], -1, l);
        if (old == -1) { g_hval[slot] = j; break; }
        slot = (slot + 1) & HMASK;
    }
    atomicAdd(&g_hist[l >> BSHIFT], 1);
}

// ---------------- single-block exclusive scan over NBK buckets ----------------
__global__ void k_scan() {
    __shared__ int sh[1024];
    int t = threadIdx.x;
    int carry = 0;
    for (int base = 0; base < NBK; base += 1024) {
        int i = base + t;
        int v = (i < NBK) ? g_hist[i] : 0;
        sh[t] = v;
        __syncthreads();
        for (int off = 1; off < 1024; off <<= 1) {
            int x = 0;
            if (t >= off) x = sh[t - off];
            __syncthreads();
            if (t >= off) sh[t] += x;
            __syncthreads();
        }
        if (i < NBK) g_scan[i] = sh[t] - v + carry;
        carry += sh[1023];
        __syncthreads();
    }
    if (t == 0) g_scan[NBK] = carry;
}

// ---------------- scatter lins into buckets (order-free; ranks are count-based) ----------------
__global__ void k_scatter() {
    int j = blockIdx.x * blockDim.x + threadIdx.x;
    if (j >= NV) return;
    int l = g_lin[j];
    int b = l >> BSHIFT;
    int p = atomicAdd(&g_bfill[b], 1);
    g_blin[g_scan[b] + p] = l;
}

// ---------------- rulebook: 27 hash lookups per voxel, compacted (k-ordered = deterministic) ----------------
__global__ void k_nbr(const int* __restrict__ inds) {
    int j = blockIdx.x * blockDim.x + threadIdx.x;
    if (j >= NV) return;
    int4 id = reinterpret_cast<const int4*>(inds)[j];
    int c = 0;
    int base = j * 27;
    #pragma unroll
    for (int dz = -1; dz <= 1; dz++) {
        int z = id.y + dz;
        #pragma unroll
        for (int dy = -1; dy <= 1; dy++) {
            int y = id.z + dy;
            #pragma unroll
            for (int dx = -1; dx <= 1; dx++) {
                int x = id.w + dx;
                if (z < 0 || z >= SZc || y < 0 || y >= SYc || x < 0 || x >= SXc) continue;
                int nl = ((id.x * SZc + z) * SYc + y) * SXc + x;
                unsigned slot = hash_of(nl);
                int r = -1;
                while (true) {
                    int key = g_hkey[slot];
                    if (key == nl) { r = g_hval[slot]; break; }
                    if (key == -1) break;
                    slot = (slot + 1) & HMASK;
                }
                if (r >= 0) {
                    int k = ((dz + 1) * 3 + (dy + 1)) * 3 + (dx + 1);
                    g_nbr[base + c] = (k << 18) | r;
                    c++;
                }
            }
        }
    }
    g_cnt[j] = c;
}

// ---------------- conv0: 4 -> 16 channels over the compacted rulebook ----------------
__global__ void k_conv0(const float* __restrict__ feats, const float* __restrict__ w_in) {
    __shared__ float w[27 * 64];   // [k][cin=4][cout=16]
    for (int i = threadIdx.x; i < 27 * 64; i += blockDim.x) w[i] = w_in[i];
    __syncthreads();
    int j = blockIdx.x * blockDim.x + threadIdx.x;
    if (j >= NV) return;
    float acc[16];
    #pragma unroll
    for (int o = 0; o < 16; o++) acc[o] = 0.f;
    int cn = g_cnt[j];
    int base = j * 27;
    for (int i = 0; i < cn; i++) {
        int p = g_nbr[base + i];
        int k = p >> 18;
        int r = p & 0x3FFFF;
        float4 f = reinterpret_cast<const float4*>(feats)[r];
        const float* wk = &w[k * 64];
        #pragma unroll
        for (int o = 0; o < 16; o++)
            acc[o] += f.x * wk[o] + f.y * wk[16 + o] + f.z * wk[32 + o] + f.w * wk[48 + o];
    }
    float4* dst = reinterpret_cast<float4*>(&g_y0[j * 16]);
    #pragma unroll
    for (int q = 0; q < 4; q++)
        dst[q] = make_float4(acc[q * 4], acc[q * 4 + 1], acc[q * 4 + 2], acc[q * 4 + 3]);
}

// ---------------- BN partial reduction (deterministic tree) ----------------
__global__ void k_bnred(int which) {
    const float* src = which ? g_xa : g_y0;
    int tid = blockIdx.x * blockDim.x + threadIdx.x;
    int stride = gridDim.x * blockDim.x;
    float s[16], q[16];
    #pragma unroll
    for (int c = 0; c < 16; c++) { s[c] = 0.f; q[c] = 0.f; }
    for (int j = tid; j < NV; j += stride) {
        const float4* r = reinterpret_cast<const float4*>(&src[j * 16]);
        #pragma unroll
        for (int p = 0; p < 4; p++) {
            float4 v = r[p];
            s[p * 4 + 0] += v.x; q[p * 4 + 0] += v.x * v.x;
            s[p * 4 + 1] += v.y; q[p * 4 + 1] += v.y * v.y;
            s[p * 4 + 2] += v.z; q[p * 4 + 2] += v.z * v.z;
            s[p * 4 + 3] += v.w; q[p * 4 + 3] += v.w * v.w;
        }
    }
    #pragma unroll
    for (int c = 0; c < 16; c++) {
        #pragma unroll
        for (int off = 16; off > 0; off >>= 1) {
            s[c] += __shfl_down_sync(0xffffffffu, s[c], off);
            q[c] += __shfl_down_sync(0xffffffffu, q[c], off);
        }
    }
    __shared__ float sm[8][32];
    int wp = threadIdx.x >> 5, lane = threadIdx.x & 31;
    if (lane == 0) {
        #pragma unroll
        for (int c = 0; c < 16; c++) { sm[wp][c] = s[c]; sm[wp][16 + c] = q[c]; }
    }
    __syncthreads();
    if (wp == 0) {
        float t = 0.f;
        #pragma unroll
        for (int k = 0; k < 8; k++) t += sm[k][lane];
        g_part[blockIdx.x * 32 + lane] = t;
    }
}

// ---------------- BN finalize: mean/var -> scale/shift ----------------
__global__ void k_bnfin(const float* __restrict__ g, const float* __restrict__ b, int which) {
    int c = threadIdx.x;
    if (c >= 16) return;
    double s = 0.0, q = 0.0;
    for (int k = 0; k < NRED; k++) { s += g_part[k * 32 + c]; q += g_part[k * 32 + 16 + c]; }
    double m = s / (double)NV;
    double v = q / (double)NV - m * m;
    double inv = 1.0 / sqrt(v + 1e-3);
    float sc = g[c] * (float)inv;
    g_ss[which * 2][c] = sc;
    g_ss[which * 2 + 1][c] = b[c] - (float)m * sc;
}

// ---------------- apply BN0 + ReLU -> x ----------------
__global__ void k_x() {
    int i = blockIdx.x * blockDim.x + threadIdx.x;   // one float4 (4 channels)
    if (i >= NV * 4) return;
    int c4 = (i & 3) * 4;
    float4 v = reinterpret_cast<const float4*>(g_y0)[i];
    v.x = fmaxf(v.x * g_ss[0][c4 + 0] + g_ss[1][c4 + 0], 0.f);
    v.y = fmaxf(v.y * g_ss[0][c4 + 1] + g_ss[1][c4 + 1], 0.f);
    v.z = fmaxf(v.z * g_ss[0][c4 + 2] + g_ss[1][c4 + 2], 0.f);
    v.w = fmaxf(v.w * g_ss[0][c4 + 3] + g_ss[1][c4 + 3], 0.f);
    reinterpret_cast<float4*>(g_x)[i] = v;
}

// ---------------- conv1: 16 -> 16 channels ----------------
__global__ void k_conv1(const float* __restrict__ w1) {
    __shared__ float w[27 * 256];  // [k][cin=16][cout=16]
    for (int i = threadIdx.x; i < 27 * 256; i += blockDim.x) w[i] = w1[i];
    __syncthreads();
    int j = blockIdx.x * blockDim.x + threadIdx.x;
    if (j >= NV) return;
    float acc[16];
    #pragma unroll
    for (int o = 0; o < 16; o++) acc[o] = 0.f;
    int cn = g_cnt[j];
    int base = j * 27;
    for (int i = 0; i < cn; i++) {
        int p = g_nbr[base + i];
        int k = p >> 18;
        int r = p & 0x3FFFF;
        const float4* xr = reinterpret_cast<const float4*>(&g_x[r * 16]);
        float xv[16];
        #pragma unroll
        for (int qq = 0; qq < 4; qq++) {
            float4 v = xr[qq];
            xv[qq * 4 + 0] = v.x; xv[qq * 4 + 1] = v.y; xv[qq * 4 + 2] = v.z; xv[qq * 4 + 3] = v.w;
        }
        const float* wk = &w[k * 256];
        #pragma unroll
        for (int c = 0; c < 16; c++) {
            #pragma unroll
            for (int o = 0; o < 16; o++) acc[o] += xv[c] * wk[c * 16 + o];
        }
    }
    float4* dst = reinterpret_cast<float4*>(&g_xa[j * 16]);
    #pragma unroll
    for (int q = 0; q < 4; q++)
        dst[q] = make_float4(acc[q * 4], acc[q * 4 + 1], acc[q * 4 + 2], acc[q * 4 + 3]);
}

// ---------------- final: rank lookup + BN1 + ReLU + duplicated scatter ----------------
__global__ void k_out(float* __restrict__ out) {
    int j = blockIdx.x * blockDim.x + threadIdx.x;
    if (j >= NV) return;
    int l = g_lin[j];
    int b = l >> BSHIFT;
    int s0 = g_scan[b], s1 = g_scan[b + 1];
    int c = 0;
    for (int t = s0; t < s1; t++) c += (g_blin[t] < l);
    int r = s0 + c;                      // rank of lin_j among all N
    const float4* xr = reinterpret_cast<const float4*>(&g_xa[r * 16]);
    float4* d0 = reinterpret_cast<float4*>(&out[(size_t)j * 16]);
    float4* d1 = reinterpret_cast<float4*>(&out[(size_t)(j + NV) * 16]);
    #pragma unroll
    for (int q = 0; q < 4; q++) {
        float4 v = xr[q];
        int c4 = q * 4;
        v.x = fmaxf(v.x * g_ss[2][c4 + 0] + g_ss[3][c4 + 0], 0.f);
        v.y = fmaxf(v.y * g_ss[2][c4 + 1] + g_ss[3][c4 + 1], 0.f);
        v.z = fmaxf(v.z * g_ss[2][c4 + 2] + g_ss[3][c4 + 2], 0.f);
        v.w = fmaxf(v.w * g_ss[2][c4 + 3] + g_ss[3][c4 + 3], 0.f);
        d0[q] = v;
        d1[q] = v;
    }
}

extern "C" void kernel_launch(void* const* d_in, const int* in_sizes, int n_in,
                              void* d_out, int out_size) {
    const float* feats = (const float*)d_in[0];
    const int*   inds  = (const int*)d_in[1];
    const float* w_in  = (const float*)d_in[2];
    const float* g0    = (const float*)d_in[3];
    const float* b0    = (const float*)d_in[4];
    const float* w1    = (const float*)d_in[5];
    const float* g1    = (const float*)d_in[6];
    const float* b1    = (const float*)d_in[7];
    // w2/g2/b2 (d_in[8..10]) are dead in the reference: cat_tensors' inverse
    // indices only ever select rows of xa.
    float* out = (float*)d_out;

    const int TB = 256;
    const int NBLK = (NV + TB - 1) / TB;

    k_init<<<(HSIZE + TB - 1) / TB, TB>>>();
    k_build<<<NBLK, TB>>>(inds);
    k_scan<<<1, 1024>>>();
    k_scatter<<<NBLK, TB>>>();
    k_nbr<<<NBLK, TB>>>(inds);
    k_conv0<<<NBLK, TB>>>(feats, w_in);
    k_bnred<<<NRED, TB>>>(0);
    k_bnfin<<<1, 32>>>(g0, b0, 0);
    k_x<<<(NV * 4 + TB - 1) / TB, TB>>>();
    k_conv1<<<NBLK, TB>>>(w1);
    k_bnred<<<NRED, TB>>>(1);
    k_bnfin<<<1, 32>>>(g1, b1, 1);
    k_out<<<NBLK, TB>>>(out);
}

// round 4
// speedup vs baseline: 1.3302x; 1.3302x over previous
#include <cuda_runtime.h>
#include <cstdint>

// Problem constants (fixed by the reference setup)
#define NV 150000          // total active voxels
#define SZc 41
#define SYc 1600
#define SXc 1408
#define HBITS 19
#define HSIZE (1 << HBITS) // 524288 hash slots (load factor ~0.29)
#define HMASK (HSIZE - 1)
#define BSHIFT 13
#define NBK 45100          // rank buckets = MAXLIN>>13 (+1); max lin 369,459,199 -> bucket 45099
#define SCANB 45           // ceil(NBK/1024)
#define CBLK 586           // ceil(NV/256) conv grid

// ---------------- static device scratch (no runtime allocation) ----------------
__device__ int   g_hkey[HSIZE];
__device__ int   g_hval[HSIZE];
__device__ int   g_lin[NV];
__device__ int   g_cnt[NV];
__device__ int   g_nbr[NV * 27];     // packed (k<<18)|row
__device__ int   g_hist[NBK];
__device__ int   g_scan[NBK + 1];
__device__ int   g_bsum[SCANB];
__device__ int   g_bfill[NBK];
__device__ int   g_blin[NV];
__device__ float g_y0[NV * 16];      // conv0 output (pre-BN)
__device__ float g_xa[NV * 16];      // conv1 output (pre-BN)
__device__ float g_part[CBLK * 32];  // per-block BN partials (sum[16], sumsq[16])
__device__ float g_ss[4][16];        // [0]=scale0 [1]=shift0 [2]=scale1 [3]=shift1
__device__ int   g_ctr0, g_ctr1;     // last-block-done counters

__device__ __forceinline__ unsigned hash_of(int key) {
    return ((unsigned)key * 2654435761u) >> (32 - HBITS);
}

// ---------------- init: clear hash keys (int4), histograms, counters ----------------
__global__ void k_init() {
    int i = blockIdx.x * blockDim.x + threadIdx.x;
    if (i < HSIZE / 4)
        reinterpret_cast<int4*>(g_hkey)[i] = make_int4(-1, -1, -1, -1);
    if (i < NBK) { g_hist[i] = 0; g_bfill[i] = 0; }
    if (i == 0) { g_ctr0 = 0; g_ctr1 = 0; }
}

// ---------------- build: linearize, hash-insert, bucket histogram ----------------
__global__ void k_build(const int* __restrict__ inds) {
    int j = blockIdx.x * blockDim.x + threadIdx.x;
    if (j >= NV) return;
    int4 id = reinterpret_cast<const int4*>(inds)[j];
    int l = ((id.x * SZc + id.y) * SYc + id.z) * SXc + id.w;
    g_lin[j] = l;
    unsigned slot = hash_of(l);
    while (true) {
        int old = atomicCAS(&g_hkey[slot], -1, l);
        if (old == -1) { g_hval[slot] = j; break; }
        slot = (slot + 1) & HMASK;
    }
    atomicAdd(&g_hist[l >> BSHIFT], 1);
}

// ---------------- scanA: per-tile (1024) exclusive scan + tile sums ----------------
__global__ void k_scanA() {
    __shared__ int sh[1024];
    int t = threadIdx.x;
    int i = blockIdx.x * 1024 + t;
    int v = (i < NBK) ? g_hist[i] : 0;
    sh[t] = v;
    __syncthreads();
    for (int off = 1; off < 1024; off <<= 1) {
        int x = 0;
        if (t >= off) x = sh[t - off];
        __syncthreads();
        if (t >= off) sh[t] += x;
        __syncthreads();
    }
    if (i < NBK) g_scan[i] = sh[t] - v;         // tile-local exclusive
    if (t == 1023) g_bsum[blockIdx.x] = sh[t];  // tile total
}

// ---------------- scanB: add tile-sum prefix (each block recomputes its tiny prefix) ----------------
__global__ void k_scanB() {
    __shared__ int off;
    if (threadIdx.x == 0) {
        int s = 0;
        for (int k = 0; k < (int)blockIdx.x; k++) s += g_bsum[k];
        off = s;
    }
    __syncthreads();
    int i = blockIdx.x * 1024 + threadIdx.x;
    if (i < NBK) g_scan[i] += off;
    if (i == NBK - 1) g_scan[NBK] = NV;         // total is always NV
}

// ---------------- prep: scatter lins into buckets + build rulebook ----------------
__global__ void k_prep(const int* __restrict__ inds) {
    int j = blockIdx.x * blockDim.x + threadIdx.x;
    if (j >= NV) return;
    int4 id = reinterpret_cast<const int4*>(inds)[j];
    int l = g_lin[j];
    // scatter (order-free; ranks later are count-based)
    int b = l >> BSHIFT;
    int p = atomicAdd(&g_bfill[b], 1);
    g_blin[g_scan[b] + p] = l;
    // rulebook: 26 hash probes (self k=13 is free), compacted, k-ordered
    int c = 0;
    int base = j * 27;
    #pragma unroll
    for (int dz = -1; dz <= 1; dz++) {
        int z = id.y + dz;
        #pragma unroll
        for (int dy = -1; dy <= 1; dy++) {
            int y = id.z + dy;
            #pragma unroll
            for (int dx = -1; dx <= 1; dx++) {
                if (dz == 0 && dy == 0 && dx == 0) {
                    g_nbr[base + c] = (13 << 18) | j;  // self always present
                    c++;
                    continue;
                }
                int x = id.w + dx;
                if (z < 0 || z >= SZc || y < 0 || y >= SYc || x < 0 || x >= SXc) continue;
                int nl = ((id.x * SZc + z) * SYc + y) * SXc + x;
                unsigned slot = hash_of(nl);
                int r = -1;
                while (true) {
                    int key = g_hkey[slot];
                    if (key == nl) { r = g_hval[slot]; break; }
                    if (key == -1) break;
                    slot = (slot + 1) & HMASK;
                }
                if (r >= 0) {
                    int k = ((dz + 1) * 3 + (dy + 1)) * 3 + (dx + 1);
                    g_nbr[base + c] = (k << 18) | r;
                    c++;
                }
            }
        }
    }
    g_cnt[j] = c;
}

// ---------------- shared: deterministic per-block BN reduction + last-block finalize ----------
__device__ __forceinline__ void bn_block_reduce_finalize(
    float acc[16], int* ctr,
    const float* __restrict__ g, const float* __restrict__ b, int which)
{
    float s[16], q[16];
    #pragma unroll
    for (int c = 0; c < 16; c++) { s[c] = acc[c]; q[c] = acc[c] * acc[c]; }
    #pragma unroll
    for (int c = 0; c < 16; c++) {
        #pragma unroll
        for (int off = 16; off > 0; off >>= 1) {
            s[c] += __shfl_down_sync(0xffffffffu, s[c], off);
            q[c] += __shfl_down_sync(0xffffffffu, q[c], off);
        }
    }
    __shared__ float sm[8][32];
    int wp = threadIdx.x >> 5, lane = threadIdx.x & 31;
    if (lane == 0) {
        #pragma unroll
        for (int c = 0; c < 16; c++) { sm[wp][c] = s[c]; sm[wp][16 + c] = q[c]; }
    }
    __syncthreads();
    if (wp == 0) {
        float t = 0.f;
        #pragma unroll
        for (int k = 0; k < 8; k++) t += sm[k][lane];
        g_part[blockIdx.x * 32 + lane] = t;
    }
    __threadfence();
    __shared__ int isLast;
    if (threadIdx.x == 0) isLast = (atomicAdd(ctr, 1) == (int)gridDim.x - 1);
    __syncthreads();
    if (isLast && threadIdx.x < 16) {
        int c = threadIdx.x;
        double ds = 0.0, dq = 0.0;
        for (int k = 0; k < CBLK; k++) {
            ds += (double)g_part[k * 32 + c];
            dq += (double)g_part[k * 32 + 16 + c];
        }
        double m = ds / (double)NV;
        double v = dq / (double)NV - m * m;
        double inv = 1.0 / sqrt(v + 1e-3);
        float sc = g[c] * (float)inv;
        g_ss[which * 2][c] = sc;
        g_ss[which * 2 + 1][c] = b[c] - (float)m * sc;
    }
}

// ---------------- conv0 (4->16) + BN0 stats/finalize fused ----------------
__global__ void k_conv0r(const float* __restrict__ feats, const float* __restrict__ w_in,
                         const float* __restrict__ g0, const float* __restrict__ b0) {
    __shared__ float w[27 * 64];   // [k][cin=4][cout=16]
    for (int i = threadIdx.x; i < 27 * 64; i += blockDim.x) w[i] = w_in[i];
    __syncthreads();
    int j = blockIdx.x * blockDim.x + threadIdx.x;
    float acc[16];
    #pragma unroll
    for (int o = 0; o < 16; o++) acc[o] = 0.f;
    if (j < NV) {
        int cn = g_cnt[j];
        int base = j * 27;
        for (int i = 0; i < cn; i++) {
            int p = g_nbr[base + i];
            int k = p >> 18;
            int r = p & 0x3FFFF;
            float4 f = reinterpret_cast<const float4*>(feats)[r];
            const float* wk = &w[k * 64];
            #pragma unroll
            for (int o = 0; o < 16; o++)
                acc[o] += f.x * wk[o] + f.y * wk[16 + o] + f.z * wk[32 + o] + f.w * wk[48 + o];
        }
        float4* dst = reinterpret_cast<float4*>(&g_y0[j * 16]);
        #pragma unroll
        for (int q = 0; q < 4; q++)
            dst[q] = make_float4(acc[q * 4], acc[q * 4 + 1], acc[q * 4 + 2], acc[q * 4 + 3]);
    }
    bn_block_reduce_finalize(acc, &g_ctr0, g0, b0, 0);
}

// ---------------- conv1 (16->16) with inline BN0+ReLU on gathers + BN1 stats fused ----------------
__global__ void k_conv1r(const float* __restrict__ w1,
                         const float* __restrict__ g1, const float* __restrict__ b1) {
    __shared__ float w[27 * 256];  // [k][cin=16][cout=16]
    __shared__ float sc0[16], sh0[16];
    for (int i = threadIdx.x; i < 27 * 256; i += blockDim.x) w[i] = w1[i];
    if (threadIdx.x < 16) { sc0[threadIdx.x] = g_ss[0][threadIdx.x]; sh0[threadIdx.x] = g_ss[1][threadIdx.x]; }
    __syncthreads();
    int j = blockIdx.x * blockDim.x + threadIdx.x;
    float acc[16];
    #pragma unroll
    for (int o = 0; o < 16; o++) acc[o] = 0.f;
    if (j < NV) {
        int cn = g_cnt[j];
        int base = j * 27;
        for (int i = 0; i < cn; i++) {
            int p = g_nbr[base + i];
            int k = p >> 18;
            int r = p & 0x3FFFF;
            const float4* xr = reinterpret_cast<const float4*>(&g_y0[r * 16]);
            float xv[16];
            #pragma unroll
            for (int qq = 0; qq < 4; qq++) {
                float4 v = xr[qq];
                int c4 = qq * 4;
                xv[c4 + 0] = fmaxf(v.x * sc0[c4 + 0] + sh0[c4 + 0], 0.f);
                xv[c4 + 1] = fmaxf(v.y * sc0[c4 + 1] + sh0[c4 + 1], 0.f);
                xv[c4 + 2] = fmaxf(v.z * sc0[c4 + 2] + sh0[c4 + 2], 0.f);
                xv[c4 + 3] = fmaxf(v.w * sc0[c4 + 3] + sh0[c4 + 3], 0.f);
            }
            const float* wk = &w[k * 256];
            #pragma unroll
            for (int c = 0; c < 16; c++) {
                #pragma unroll
                for (int o = 0; o < 16; o++) acc[o] += xv[c] * wk[c * 16 + o];
            }
        }
        float4* dst = reinterpret_cast<float4*>(&g_xa[j * 16]);
        #pragma unroll
        for (int q = 0; q < 4; q++)
            dst[q] = make_float4(acc[q * 4], acc[q * 4 + 1], acc[q * 4 + 2], acc[q * 4 + 3]);
    }
    bn_block_reduce_finalize(acc, &g_ctr1, g1, b1, 1);
}

// ---------------- final: rank lookup + BN1 + ReLU + duplicated scatter ----------------
__global__ void k_out(float* __restrict__ out) {
    int j = blockIdx.x * blockDim.x + threadIdx.x;
    if (j >= NV) return;
    int l = g_lin[j];
    int b = l >> BSHIFT;
    int s0 = g_scan[b], s1 = g_scan[b + 1];
    int c = 0;
    for (int t = s0; t < s1; t++) c += (g_blin[t] < l);
    int r = s0 + c;                      // rank of lin_j among all N
    const float4* xr = reinterpret_cast<const float4*>(&g_xa[r * 16]);
    float4* d0 = reinterpret_cast<float4*>(&out[(size_t)j * 16]);
    float4* d1 = reinterpret_cast<float4*>(&out[(size_t)(j + NV) * 16]);
    #pragma unroll
    for (int q = 0; q < 4; q++) {
        float4 v = xr[q];
        int c4 = q * 4;
        v.x = fmaxf(v.x * g_ss[2][c4 + 0] + g_ss[3][c4 + 0], 0.f);
        v.y = fmaxf(v.y * g_ss[2][c4 + 1] + g_ss[3][c4 + 1], 0.f);
        v.z = fmaxf(v.z * g_ss[2][c4 + 2] + g_ss[3][c4 + 2], 0.f);
        v.w = fmaxf(v.w * g_ss[2][c4 + 3] + g_ss[3][c4 + 3], 0.f);
        d0[q] = v;
        d1[q] = v;
    }
}

extern "C" void kernel_launch(void* const* d_in, const int* in_sizes, int n_in,
                              void* d_out, int out_size) {
    const float* feats = (const float*)d_in[0];
    const int*   inds  = (const int*)d_in[1];
    const float* w_in  = (const float*)d_in[2];
    const float* g0    = (const float*)d_in[3];
    const float* b0    = (const float*)d_in[4];
    const float* w1    = (const float*)d_in[5];
    const float* g1    = (const float*)d_in[6];
    const float* b1    = (const float*)d_in[7];
    // w2/g2/b2 (d_in[8..10]) are dead in the reference: cat_tensors' inverse
    // indices only ever select rows of xa.
    float* out = (float*)d_out;

    const int TB = 256;

    k_init<<<(HSIZE / 4 + TB - 1) / TB, TB>>>();
    k_build<<<CBLK, TB>>>(inds);
    k_scanA<<<SCANB, 1024>>>();
    k_scanB<<<SCANB, 1024>>>();
    k_prep<<<CBLK, TB>>>(inds);
    k_conv0r<<<CBLK, TB>>>(feats, w_in, g0, b0);
    k_conv1r<<<CBLK, TB>>>(w1, g1, b1);
    k_out<<<CBLK, TB>>>(out);
}